// round 10
// baseline (speedup 1.0000x reference)
#include <cuda_runtime.h>
#include <cuda_fp16.h>
#include <mma.h>
#include <cstdint>

using namespace nvcuda;

#define N_MESH 40962
#define N_GRID 262144
#define N_EDGE 786432

// ------------------------------ device scratch ------------------------------
__device__ float  g_agg[(size_t)N_GRID * 128];
__device__ __half g_W1e[384 * 256];   // [K][N], fp16-RN pre-rounded
__device__ __half g_W2e[256 * 128];
__device__ __half g_W1n[256 * 256];
__device__ __half g_W2n[256 * 128];

#define MT    128
#define NTHR  512

// ------------------------------ smem layout (BYTE offsets) ------------------
// GEMM1 phase:   A [2560,23040) double 10240, B1 [23040,56832) double 16896
// post-GEMM1:    HH [2560,70144)  (overlays dead A+B1)
//                B2 [70144,87552) double 8704
//                SCR [87552,108032) 16 x 1280
// post-GEMM2:    Y  [2560,70144)  (overlays dead HH; needs 67584)
#define SM_CONST_B1 0
#define SM_CONST_B2 1024
#define SM_CONST_G  1536
#define SM_CONST_BT 2048
#define SM_A(b)    (2560 + (b) * 10240)    // half, 128 x 40, double
#define SM_B1(s)   (23040 + (s) * 16896)   // half, 32 x 264, double
#define SM_HH      2560                     // half, 128 x 264 = 67584
#define SM_B2(s)   (70144 + (s) * 8704)    // half, 32 x 136, double
#define SM_SCR(w)  (87552 + (w) * 1280)    // float, 16 x 20 per warp
#define SM_Y       2560                     // float, 128 x 132 = 67584
#define SMEM_BYTES 108032                   // x2 CTAs = 216,064 <= 227KB

#define LDA   40    // halves
#define LDB1  264   // halves
#define LDB2  136   // halves
#define LDHH  264   // halves
#define LDY   132   // floats
#define LDSCR 20    // floats

// ------------------------------ helpers -------------------------------------
__device__ __forceinline__ uint32_t smem_u32(const void* p) {
    uint32_t a;
    asm("{ .reg .u64 t; cvta.to.shared.u64 t, %1; cvt.u32.u64 %0, t; }" : "=r"(a) : "l"(p));
    return a;
}
__device__ __forceinline__ void cpa16(uint32_t s, const void* g) {
    asm volatile("cp.async.cg.shared.global [%0], [%1], 16;" :: "r"(s), "l"(g) : "memory");
}
__device__ __forceinline__ void cp_commit() {
    asm volatile("cp.async.commit_group;" ::: "memory");
}
__device__ __forceinline__ void cp_wait0() {
    asm volatile("cp.async.wait_group 0;" ::: "memory");
}
__device__ __forceinline__ void red_add_v4(float* p, float4 v) {
    asm volatile("red.global.add.v4.f32 [%0], {%1, %2, %3, %4};"
                 :: "l"(p), "f"(v.x), "f"(v.y), "f"(v.z), "f"(v.w) : "memory");
}
__device__ __forceinline__ uint4 pack8h(float4 a, float4 b) {
    __half2 h0 = __floats2half2_rn(a.x, a.y);
    __half2 h1 = __floats2half2_rn(a.z, a.w);
    __half2 h2 = __floats2half2_rn(b.x, b.y);
    __half2 h3 = __floats2half2_rn(b.z, b.w);
    uint4 u;
    u.x = *reinterpret_cast<uint32_t*>(&h0);
    u.y = *reinterpret_cast<uint32_t*>(&h1);
    u.z = *reinterpret_cast<uint32_t*>(&h2);
    u.w = *reinterpret_cast<uint32_t*>(&h3);
    return u;
}
__device__ __forceinline__ float4 silu4(float4 x) {
    float4 s;
    s.x = x.x / (1.f + __expf(-x.x)); s.y = x.y / (1.f + __expf(-x.y));
    s.z = x.z / (1.f + __expf(-x.z)); s.w = x.w / (1.f + __expf(-x.w));
    return s;
}

typedef wmma::fragment<wmma::matrix_a, 16, 16, 16, __half, wmma::row_major> AFrag;
typedef wmma::fragment<wmma::matrix_b, 16, 16, 16, __half, wmma::row_major> BFrag;
typedef wmma::fragment<wmma::accumulator, 16, 16, 16, float> CFrag;

// ------------------------------ prep kernels --------------------------------
__global__ void zero_agg_kernel() {
    size_t i = (size_t)blockIdx.x * blockDim.x + threadIdx.x;
    reinterpret_cast<float4*>(g_agg)[i] = make_float4(0.f, 0.f, 0.f, 0.f);
}
__global__ void prep_kernel(const float* __restrict__ eW1, const float* __restrict__ eW2,
                            const float* __restrict__ nW1, const float* __restrict__ nW2) {
    int i = blockIdx.x * blockDim.x + threadIdx.x;
    if (i < 98304)       g_W1e[i]          = __float2half_rn(eW1[i]);
    else if (i < 131072) g_W2e[i - 98304]  = __float2half_rn(eW2[i - 98304]);
    else if (i < 196608) g_W1n[i - 131072] = __float2half_rn(nW1[i - 131072]);
    else if (i < 229376) g_W2n[i - 196608] = __float2half_rn(nW2[i - 196608]);
}

// ------------------------------ edge kernel ---------------------------------
// tile = 128 edges, 512 threads (16 warps: 4M x 4N), 2 CTAs/SM.
// GEMM1 [128,384]x[384,256] (12 K32 chunks) -> SiLU -> GEMM2 [128,256]x[256,128]
// (8 K32 chunks) -> +b2 -> LN -> red.v4 scatter
__global__ void __launch_bounds__(NTHR, 2)
edge_kernel(const float* __restrict__ efeat, const float* __restrict__ gridf,
            const float* __restrict__ mesh, const int* __restrict__ src,
            const int* __restrict__ dst,
            const float* __restrict__ b1, const float* __restrict__ b2,
            const float* __restrict__ gam, const float* __restrict__ bet)
{
    extern __shared__ char smc[];
    const uint32_t sb = smem_u32(smc);
    const int tid  = threadIdx.x;
    const int warp = tid >> 5, lane = tid & 31;
    const int wm = warp >> 2, wn = warp & 3;
    const int e0 = blockIdx.x * MT;

    if (tid < 64) ((float4*)(smc + SM_CONST_B1))[tid] = ((const float4*)b1)[tid];
    else if (tid < 96)  ((float4*)(smc + SM_CONST_B2))[tid - 64] = ((const float4*)b2)[tid - 64];
    else if (tid < 128) ((float4*)(smc + SM_CONST_G ))[tid - 96] = ((const float4*)gam)[tid - 96];
    else if (tid < 160) ((float4*)(smc + SM_CONST_BT))[tid - 128] = ((const float4*)bet)[tid - 128];

    // gather: 4 threads per row, 8 floats each per K32 chunk
    const int r  = tid >> 2;
    const int cb = (tid & 3) * 8;
    const int sidx = __ldg(&src[e0 + r]);
    const int didx = __ldg(&dst[e0 + r]);
    const float* rowE = efeat + (size_t)(e0 + r) * 128;
    const float* rowM = mesh  + (size_t)sidx * 128;
    const float* rowG = gridf + (size_t)didx * 128;

    float4 v0, v1;
    auto ldgA = [&](int c) {
        const float* rp = (c < 4) ? rowE : (c < 8) ? rowM : rowG;
        const float4* gp = (const float4*)(rp + (c & 3) * 32 + cb);
        v0 = __ldg(gp); v1 = __ldg(gp + 1);
    };
    auto stsA = [&](int c) {
        *(uint4*)(smc + SM_A(c & 1) + (r * LDA + cb) * 2) = pack8h(v0, v1);
    };
    auto stageB1 = [&](int c) {
        uint32_t bb = sb + SM_B1(c & 1);
        const __half* gw = g_W1e + c * 32 * 256;
        #pragma unroll
        for (int i = 0; i < 2; ++i) {
            int id = tid + NTHR * i; int rw = id >> 5, c16 = id & 31;
            cpa16(bb + (uint32_t)(rw * LDB1 + c16 * 8) * 2, gw + rw * 256 + c16 * 8);
        }
    };
    auto stageB2 = [&](int c) {
        uint32_t bb = sb + SM_B2(c & 1);
        const __half* gw = g_W2e + c * 32 * 128;
        int rw = tid >> 4, c16 = tid & 15;
        cpa16(bb + (uint32_t)(rw * LDB2 + c16 * 8) * 2, gw + rw * 128 + c16 * 8);
    };

    // ---------------- GEMM1: [128,384]x[384,256], 12 K32 chunks ----------------
    CFrag acc[2][4];
    #pragma unroll
    for (int i = 0; i < 2; i++)
        #pragma unroll
        for (int j = 0; j < 4; j++) wmma::fill_fragment(acc[i][j], 0.f);

    ldgA(0); stageB1(0); cp_commit(); stsA(0); ldgA(1);

    #pragma unroll 1
    for (int c = 0; c < 12; ++c) {
        cp_wait0();
        __syncthreads();
        if (c + 1 < 12) { stageB1(c + 1); cp_commit(); }
        const __half* ab = (const __half*)(smc + SM_A(c & 1));
        const __half* bb = (const __half*)(smc + SM_B1(c & 1));
        #pragma unroll
        for (int kk = 0; kk < 32; kk += 16) {
            AFrag a0, a1;
            wmma::load_matrix_sync(a0, ab + (wm * 32)      * LDA + kk, LDA);
            wmma::load_matrix_sync(a1, ab + (wm * 32 + 16) * LDA + kk, LDA);
            #pragma unroll
            for (int j = 0; j < 4; j++) {
                BFrag b;
                wmma::load_matrix_sync(b, bb + kk * LDB1 + wn * 64 + j * 16, LDB1);
                wmma::mma_sync(acc[0][j], a0, b, acc[0][j]);
                wmma::mma_sync(acc[1][j], a1, b, acc[1][j]);
            }
        }
        if (c + 1 < 12) { stsA(c + 1); if (c + 2 < 12) ldgA(c + 2); }
    }
    __syncthreads();          // GEMM1 done; A + B1 regions dead -> HH

    stageB2(0); cp_commit();  // prefetch GEMM2 chunk 0 behind the transition

    // ---------------- transition: acc -> (bias,SiLU) -> HH fp16 --------------
    {
        float* scr = (float*)(smc + SM_SCR(warp));
        const float* sb1 = (const float*)(smc + SM_CONST_B1);
        const int rr = lane >> 1, ch = (lane & 1) * 8;
        #pragma unroll
        for (int i = 0; i < 2; i++)
            #pragma unroll
            for (int j = 0; j < 4; j++) {
                wmma::store_matrix_sync(scr, acc[i][j], LDSCR, wmma::mem_row_major);
                __syncwarp();
                const float* p = scr + rr * LDSCR + ch;
                float4 x0 = *(const float4*)(p);
                float4 x1 = *(const float4*)(p + 4);
                int cbase = wn * 64 + j * 16 + ch;
                float4 bb0 = *(const float4*)(sb1 + cbase);
                float4 bb1 = *(const float4*)(sb1 + cbase + 4);
                x0.x += bb0.x; x0.y += bb0.y; x0.z += bb0.z; x0.w += bb0.w;
                x1.x += bb1.x; x1.y += bb1.y; x1.z += bb1.z; x1.w += bb1.w;
                int rowg = wm * 32 + i * 16 + rr;
                *(uint4*)(smc + SM_HH + (rowg * LDHH + cbase) * 2) =
                    pack8h(silu4(x0), silu4(x1));
                __syncwarp();
            }
    }

    // ---------------- GEMM2: [128,256]x[256,128], 8 K32 chunks ----------------
    CFrag acc2[2][2];
    #pragma unroll
    for (int i = 0; i < 2; i++)
        #pragma unroll
        for (int j = 0; j < 2; j++) wmma::fill_fragment(acc2[i][j], 0.f);

    const __half* hh = (const __half*)(smc + SM_HH);
    #pragma unroll 1
    for (int c = 0; c < 8; ++c) {
        cp_wait0();
        __syncthreads();      // HH visible (c=0); B2 buffer free
        if (c + 1 < 8) { stageB2(c + 1); cp_commit(); }
        const __half* bb = (const __half*)(smc + SM_B2(c & 1));
        #pragma unroll
        for (int kk = 0; kk < 32; kk += 16) {
            AFrag a0, a1;
            wmma::load_matrix_sync(a0, hh + (wm * 32)      * LDHH + c * 32 + kk, LDHH);
            wmma::load_matrix_sync(a1, hh + (wm * 32 + 16) * LDHH + c * 32 + kk, LDHH);
            #pragma unroll
            for (int j = 0; j < 2; j++) {
                BFrag b;
                wmma::load_matrix_sync(b, bb + kk * LDB2 + wn * 32 + j * 16, LDB2);
                wmma::mma_sync(acc2[0][j], a0, b, acc2[0][j]);
                wmma::mma_sync(acc2[1][j], a1, b, acc2[1][j]);
            }
        }
    }
    __syncthreads();          // all GEMM2 MMAs done; HH dead -> Y
    float* yf = (float*)(smc + SM_Y);
    #pragma unroll
    for (int i = 0; i < 2; i++)
        #pragma unroll
        for (int j = 0; j < 2; j++)
            wmma::store_matrix_sync(yf + (wm * 32 + i * 16) * LDY + wn * 32 + j * 16,
                                    acc2[i][j], LDY, wmma::mem_row_major);
    __syncthreads();

    // ---------------- +b2, LN, vector-red scatter ----------------
    float4 bb2 = *(const float4*)(smc + SM_CONST_B2 + lane * 16);
    float4 gg  = *(const float4*)(smc + SM_CONST_G  + lane * 16);
    float4 bt  = *(const float4*)(smc + SM_CONST_BT + lane * 16);
    #pragma unroll 1
    for (int i = 0; i < 8; i++) {
        int row = warp * 8 + i;
        float4 v = *(const float4*)(yf + row * LDY + lane * 4);
        v.x += bb2.x; v.y += bb2.y; v.z += bb2.z; v.w += bb2.w;
        float sum = v.x + v.y + v.z + v.w;
        float sq  = v.x * v.x + v.y * v.y + v.z * v.z + v.w * v.w;
        #pragma unroll
        for (int o = 16; o > 0; o >>= 1) {
            sum += __shfl_xor_sync(0xFFFFFFFFu, sum, o);
            sq  += __shfl_xor_sync(0xFFFFFFFFu, sq,  o);
        }
        float mean = sum * (1.f / 128.f);
        float rstd = rsqrtf(sq * (1.f / 128.f) - mean * mean + 1e-5f);
        int dn = __ldg(&dst[e0 + row]);
        float4 o;
        o.x = (v.x - mean) * rstd * gg.x + bt.x;
        o.y = (v.y - mean) * rstd * gg.y + bt.y;
        o.z = (v.z - mean) * rstd * gg.z + bt.z;
        o.w = (v.w - mean) * rstd * gg.w + bt.w;
        red_add_v4(g_agg + (size_t)dn * 128 + lane * 4, o);
    }
}

// ------------------------------ node kernel ---------------------------------
__global__ void __launch_bounds__(NTHR, 2)
node_kernel(const float* __restrict__ gridf,
            const float* __restrict__ b1, const float* __restrict__ b2,
            const float* __restrict__ gam, const float* __restrict__ bet,
            float* __restrict__ out)
{
    extern __shared__ char smc[];
    const uint32_t sb = smem_u32(smc);
    const int tid  = threadIdx.x;
    const int warp = tid >> 5, lane = tid & 31;
    const int wm = warp >> 2, wn = warp & 3;
    const int n0 = blockIdx.x * MT;

    if (tid < 64) ((float4*)(smc + SM_CONST_B1))[tid] = ((const float4*)b1)[tid];
    else if (tid < 96)  ((float4*)(smc + SM_CONST_B2))[tid - 64] = ((const float4*)b2)[tid - 64];
    else if (tid < 128) ((float4*)(smc + SM_CONST_G ))[tid - 96] = ((const float4*)gam)[tid - 96];
    else if (tid < 160) ((float4*)(smc + SM_CONST_BT))[tid - 128] = ((const float4*)bet)[tid - 128];

    const int r  = tid >> 2;
    const int cb = (tid & 3) * 8;
    const float* rowA = g_agg + (size_t)(n0 + r) * 128;
    const float* rowG = gridf + (size_t)(n0 + r) * 128;

    float4 v0, v1;
    auto ldgA = [&](int c) {
        const float* rp = (c < 4) ? rowA : rowG;
        const float4* gp = (const float4*)(rp + (c & 3) * 32 + cb);
        v0 = __ldg(gp); v1 = __ldg(gp + 1);
    };
    auto stsA = [&](int c) {
        *(uint4*)(smc + SM_A(c & 1) + (r * LDA + cb) * 2) = pack8h(v0, v1);
    };
    auto stageB1 = [&](int c) {
        uint32_t bb = sb + SM_B1(c & 1);
        const __half* gw = g_W1n + c * 32 * 256;
        #pragma unroll
        for (int i = 0; i < 2; ++i) {
            int id = tid + NTHR * i; int rw = id >> 5, c16 = id & 31;
            cpa16(bb + (uint32_t)(rw * LDB1 + c16 * 8) * 2, gw + rw * 256 + c16 * 8);
        }
    };
    auto stageB2 = [&](int c) {
        uint32_t bb = sb + SM_B2(c & 1);
        const __half* gw = g_W2n + c * 32 * 128;
        int rw = tid >> 4, c16 = tid & 15;
        cpa16(bb + (uint32_t)(rw * LDB2 + c16 * 8) * 2, gw + rw * 128 + c16 * 8);
    };

    // ---------------- GEMM1: [128,256]x[256,256], 8 K32 chunks ----------------
    CFrag acc[2][4];
    #pragma unroll
    for (int i = 0; i < 2; i++)
        #pragma unroll
        for (int j = 0; j < 4; j++) wmma::fill_fragment(acc[i][j], 0.f);

    ldgA(0); stageB1(0); cp_commit(); stsA(0); ldgA(1);

    #pragma unroll 1
    for (int c = 0; c < 8; ++c) {
        cp_wait0();
        __syncthreads();
        if (c + 1 < 8) { stageB1(c + 1); cp_commit(); }
        const __half* ab = (const __half*)(smc + SM_A(c & 1));
        const __half* bb = (const __half*)(smc + SM_B1(c & 1));
        #pragma unroll
        for (int kk = 0; kk < 32; kk += 16) {
            AFrag a0, a1;
            wmma::load_matrix_sync(a0, ab + (wm * 32)      * LDA + kk, LDA);
            wmma::load_matrix_sync(a1, ab + (wm * 32 + 16) * LDA + kk, LDA);
            #pragma unroll
            for (int j = 0; j < 4; j++) {
                BFrag b;
                wmma::load_matrix_sync(b, bb + kk * LDB1 + wn * 64 + j * 16, LDB1);
                wmma::mma_sync(acc[0][j], a0, b, acc[0][j]);
                wmma::mma_sync(acc[1][j], a1, b, acc[1][j]);
            }
        }
        if (c + 1 < 8) { stsA(c + 1); if (c + 2 < 8) ldgA(c + 2); }
    }
    __syncthreads();

    stageB2(0); cp_commit();

    // ---------------- transition: acc -> (bias,SiLU) -> HH fp16 --------------
    {
        float* scr = (float*)(smc + SM_SCR(warp));
        const float* sb1 = (const float*)(smc + SM_CONST_B1);
        const int rr = lane >> 1, ch = (lane & 1) * 8;
        #pragma unroll
        for (int i = 0; i < 2; i++)
            #pragma unroll
            for (int j = 0; j < 4; j++) {
                wmma::store_matrix_sync(scr, acc[i][j], LDSCR, wmma::mem_row_major);
                __syncwarp();
                const float* p = scr + rr * LDSCR + ch;
                float4 x0 = *(const float4*)(p);
                float4 x1 = *(const float4*)(p + 4);
                int cbase = wn * 64 + j * 16 + ch;
                float4 bb0 = *(const float4*)(sb1 + cbase);
                float4 bb1 = *(const float4*)(sb1 + cbase + 4);
                x0.x += bb0.x; x0.y += bb0.y; x0.z += bb0.z; x0.w += bb0.w;
                x1.x += bb1.x; x1.y += bb1.y; x1.z += bb1.z; x1.w += bb1.w;
                int rowg = wm * 32 + i * 16 + rr;
                *(uint4*)(smc + SM_HH + (rowg * LDHH + cbase) * 2) =
                    pack8h(silu4(x0), silu4(x1));
                __syncwarp();
            }
    }

    // ---------------- GEMM2: [128,256]x[256,128], 8 K32 chunks ----------------
    CFrag acc2[2][2];
    #pragma unroll
    for (int i = 0; i < 2; i++)
        #pragma unroll
        for (int j = 0; j < 2; j++) wmma::fill_fragment(acc2[i][j], 0.f);

    const __half* hh = (const __half*)(smc + SM_HH);
    #pragma unroll 1
    for (int c = 0; c < 8; ++c) {
        cp_wait0();
        __syncthreads();
        if (c + 1 < 8) { stageB2(c + 1); cp_commit(); }
        const __half* bb = (const __half*)(smc + SM_B2(c & 1));
        #pragma unroll
        for (int kk = 0; kk < 32; kk += 16) {
            AFrag a0, a1;
            wmma::load_matrix_sync(a0, hh + (wm * 32)      * LDHH + c * 32 + kk, LDHH);
            wmma::load_matrix_sync(a1, hh + (wm * 32 + 16) * LDHH + c * 32 + kk, LDHH);
            #pragma unroll
            for (int j = 0; j < 2; j++) {
                BFrag b;
                wmma::load_matrix_sync(b, bb + kk * LDB2 + wn * 32 + j * 16, LDB2);
                wmma::mma_sync(acc2[0][j], a0, b, acc2[0][j]);
                wmma::mma_sync(acc2[1][j], a1, b, acc2[1][j]);
            }
        }
    }
    __syncthreads();
    float* yf = (float*)(smc + SM_Y);
    #pragma unroll
    for (int i = 0; i < 2; i++)
        #pragma unroll
        for (int j = 0; j < 2; j++)
            wmma::store_matrix_sync(yf + (wm * 32 + i * 16) * LDY + wn * 32 + j * 16,
                                    acc2[i][j], LDY, wmma::mem_row_major);
    __syncthreads();

    // ---------------- +b2, LN, affine, +residual ----------------
    float4 bb2 = *(const float4*)(smc + SM_CONST_B2 + lane * 16);
    float4 gg  = *(const float4*)(smc + SM_CONST_G  + lane * 16);
    float4 bt  = *(const float4*)(smc + SM_CONST_BT + lane * 16);
    #pragma unroll 1
    for (int i = 0; i < 8; i++) {
        int row = warp * 8 + i;
        float4 v = *(const float4*)(yf + row * LDY + lane * 4);
        v.x += bb2.x; v.y += bb2.y; v.z += bb2.z; v.w += bb2.w;
        float sum = v.x + v.y + v.z + v.w;
        float sq  = v.x * v.x + v.y * v.y + v.z * v.z + v.w * v.w;
        #pragma unroll
        for (int o = 16; o > 0; o >>= 1) {
            sum += __shfl_xor_sync(0xFFFFFFFFu, sum, o);
            sq  += __shfl_xor_sync(0xFFFFFFFFu, sq,  o);
        }
        float mean = sum * (1.f / 128.f);
        float rstd = rsqrtf(sq * (1.f / 128.f) - mean * mean + 1e-5f);
        size_t base = (size_t)(n0 + row) * 128;
        float4 gv = __ldg((const float4*)(gridf + base) + lane);
        float4 o;
        o.x = (v.x - mean) * rstd * gg.x + bt.x + gv.x;
        o.y = (v.y - mean) * rstd * gg.y + bt.y + gv.y;
        o.z = (v.z - mean) * rstd * gg.z + bt.z + gv.z;
        o.w = (v.w - mean) * rstd * gg.w + bt.w + gv.w;
        *((float4*)(out + base) + lane) = o;
    }
}

// ------------------------------ launch --------------------------------------
extern "C" void kernel_launch(void* const* d_in, const int* in_sizes, int n_in,
                              void* d_out, int out_size)
{
    const float* efeat = (const float*)d_in[0];
    const float* gridf = (const float*)d_in[1];
    const float* mesh  = (const float*)d_in[2];
    const int*   src   = (const int*)d_in[3];
    const int*   dst   = (const int*)d_in[4];
    const float* eW1   = (const float*)d_in[5];
    const float* eb1   = (const float*)d_in[6];
    const float* eW2   = (const float*)d_in[7];
    const float* eb2   = (const float*)d_in[8];
    const float* eg    = (const float*)d_in[9];
    const float* ebeta = (const float*)d_in[10];
    const float* nW1   = (const float*)d_in[11];
    const float* nb1   = (const float*)d_in[12];
    const float* nW2   = (const float*)d_in[13];
    const float* nb2   = (const float*)d_in[14];
    const float* ng    = (const float*)d_in[15];
    const float* nbeta = (const float*)d_in[16];
    float* out = (float*)d_out;

    cudaFuncSetAttribute(edge_kernel, cudaFuncAttributeMaxDynamicSharedMemorySize, SMEM_BYTES);
    cudaFuncSetAttribute(node_kernel, cudaFuncAttributeMaxDynamicSharedMemorySize, SMEM_BYTES);

    zero_agg_kernel<<<8192, 1024>>>();
    prep_kernel<<<896, 256>>>(eW1, eW2, nW1, nW2);
    edge_kernel<<<N_EDGE / MT, NTHR, SMEM_BYTES>>>(efeat, gridf, mesh, src, dst,
                                                   eb1, eb2, eg, ebeta);
    node_kernel<<<N_GRID / MT, NTHR, SMEM_BYTES>>>(gridf, nb1, nb2, ng, nbeta, out);
}

// round 11
// speedup vs baseline: 1.9418x; 1.9418x over previous
#include <cuda_runtime.h>
#include <cuda_fp16.h>
#include <mma.h>
#include <cstdint>

using namespace nvcuda;

#define N_MESH 40962
#define N_GRID 262144
#define N_EDGE 786432

// ------------------------------ device scratch ------------------------------
__device__ float  g_agg[(size_t)N_GRID * 128];
__device__ __half g_W1e[384 * 256];   // [K][N], fp16-RN pre-rounded
__device__ __half g_W2e[256 * 128];
__device__ __half g_W1n[256 * 256];
__device__ __half g_W2n[256 * 128];

#define MT    64
#define NTHR  128

// ------------------------------ smem layout (BYTE offsets) ------------------
#define SM_CONST_B1 0
#define SM_CONST_B2 1024
#define SM_CONST_G  1536
#define SM_CONST_BT 2048
#define SM_A(b)    (2560 + (b) * 5120)     // half, 64 x 40, double
#define SM_B1(s)   (12800 + (s) * 16896)   // half, 32 x 264, double
#define SM_HH      12800                    // half, 64 x 264 = 33792 (over dead B1)
#define SM_B2(s)   (46592 + (s) * 8704)    // half, 32 x 136, double
#define SM_SCR(w)  (64000 + (w) * 1280)    // float, 16 x 20 per warp (4 warps)
#define SM_Y       2560                     // float, 64 x 132 (over dead A/HH)
#define SMEM_BYTES 69120                    // x2 CTAs = 138,240 <= 227KB

#define LDA   40    // halves
#define LDB1  264   // halves
#define LDB2  136   // halves
#define LDHH  264   // halves
#define LDY   132   // floats
#define LDSCR 20    // floats

// ------------------------------ helpers -------------------------------------
__device__ __forceinline__ uint32_t smem_u32(const void* p) {
    uint32_t a;
    asm("{ .reg .u64 t; cvta.to.shared.u64 t, %1; cvt.u32.u64 %0, t; }" : "=r"(a) : "l"(p));
    return a;
}
__device__ __forceinline__ void cpa16(uint32_t s, const void* g) {
    asm volatile("cp.async.cg.shared.global [%0], [%1], 16;" :: "r"(s), "l"(g) : "memory");
}
__device__ __forceinline__ void cp_commit() {
    asm volatile("cp.async.commit_group;" ::: "memory");
}
__device__ __forceinline__ void cp_wait0() {
    asm volatile("cp.async.wait_group 0;" ::: "memory");
}
__device__ __forceinline__ void red_add_v4(float* p, float4 v) {
    asm volatile("red.global.add.v4.f32 [%0], {%1, %2, %3, %4};"
                 :: "l"(p), "f"(v.x), "f"(v.y), "f"(v.z), "f"(v.w) : "memory");
}
__device__ __forceinline__ uint4 pack8h(float4 a, float4 b) {
    __half2 h0 = __floats2half2_rn(a.x, a.y);
    __half2 h1 = __floats2half2_rn(a.z, a.w);
    __half2 h2 = __floats2half2_rn(b.x, b.y);
    __half2 h3 = __floats2half2_rn(b.z, b.w);
    uint4 u;
    u.x = *reinterpret_cast<uint32_t*>(&h0);
    u.y = *reinterpret_cast<uint32_t*>(&h1);
    u.z = *reinterpret_cast<uint32_t*>(&h2);
    u.w = *reinterpret_cast<uint32_t*>(&h3);
    return u;
}
__device__ __forceinline__ float4 silu4(float4 x) {
    float4 s;
    s.x = x.x / (1.f + __expf(-x.x)); s.y = x.y / (1.f + __expf(-x.y));
    s.z = x.z / (1.f + __expf(-x.z)); s.w = x.w / (1.f + __expf(-x.w));
    return s;
}

typedef wmma::fragment<wmma::matrix_a, 16, 16, 16, __half, wmma::row_major> AFrag;
typedef wmma::fragment<wmma::matrix_b, 16, 16, 16, __half, wmma::row_major> BFrag;
typedef wmma::fragment<wmma::accumulator, 16, 16, 16, float> CFrag;

// ------------------------------ prep kernels --------------------------------
__global__ void zero_agg_kernel() {
    size_t i = (size_t)blockIdx.x * blockDim.x + threadIdx.x;
    reinterpret_cast<float4*>(g_agg)[i] = make_float4(0.f, 0.f, 0.f, 0.f);
}
__global__ void prep_kernel(const float* __restrict__ eW1, const float* __restrict__ eW2,
                            const float* __restrict__ nW1, const float* __restrict__ nW2) {
    int i = blockIdx.x * blockDim.x + threadIdx.x;
    if (i < 98304)       g_W1e[i]          = __float2half_rn(eW1[i]);
    else if (i < 131072) g_W2e[i - 98304]  = __float2half_rn(eW2[i - 98304]);
    else if (i < 196608) g_W1n[i - 131072] = __float2half_rn(nW1[i - 131072]);
    else if (i < 229376) g_W2n[i - 196608] = __float2half_rn(nW2[i - 196608]);
}

// ------------------------------ edge kernel ---------------------------------
// tile = 64 edges, 128 threads (4 warps, each a 64x64 GEMM1 strip).
__global__ void __launch_bounds__(NTHR, 2)
edge_kernel(const float* __restrict__ efeat, const float* __restrict__ gridf,
            const float* __restrict__ mesh, const int* __restrict__ src,
            const int* __restrict__ dst,
            const float* __restrict__ b1, const float* __restrict__ b2,
            const float* __restrict__ gam, const float* __restrict__ bet)
{
    extern __shared__ char smc[];
    const uint32_t sb = smem_u32(smc);
    const int tid  = threadIdx.x;
    const int warp = tid >> 5, lane = tid & 31;
    const int e0 = blockIdx.x * MT;

    if (tid < 64) ((float4*)(smc + SM_CONST_B1))[tid] = ((const float4*)b1)[tid];
    else if (tid < 96)  ((float4*)(smc + SM_CONST_B2))[tid - 64] = ((const float4*)b2)[tid - 64];
    else if (tid < 128) ((float4*)(smc + SM_CONST_G ))[tid - 96] = ((const float4*)gam)[tid - 96];
    if (tid < 32) ((float4*)(smc + SM_CONST_BT))[tid] = ((const float4*)bet)[tid];

    // gather: 2 threads per row, 16 floats each per K32 chunk
    const int r  = tid >> 1;
    const int cb = (tid & 1) * 16;
    const int sidx = __ldg(&src[e0 + r]);
    const int didx = __ldg(&dst[e0 + r]);
    const float* rowE = efeat + (size_t)(e0 + r) * 128;
    const float* rowM = mesh  + (size_t)sidx * 128;
    const float* rowG = gridf + (size_t)didx * 128;

    float4 v0, v1, v2, v3;
    auto ldgA = [&](int c) {
        const float* rp = (c < 4) ? rowE : (c < 8) ? rowM : rowG;
        const float4* gp = (const float4*)(rp + (c & 3) * 32 + cb);
        v0 = __ldg(gp); v1 = __ldg(gp + 1); v2 = __ldg(gp + 2); v3 = __ldg(gp + 3);
    };
    auto stsA = [&](int c) {
        char* d = smc + SM_A(c & 1) + (r * LDA + cb) * 2;
        *(uint4*)(d)      = pack8h(v0, v1);
        *(uint4*)(d + 16) = pack8h(v2, v3);
    };
    auto stageB1 = [&](int c) {
        uint32_t bb = sb + SM_B1(c & 1);
        const __half* gw = g_W1e + c * 32 * 256;
        #pragma unroll
        for (int i = 0; i < 8; ++i) {
            int id = tid + NTHR * i; int rw = id >> 5, c16 = id & 31;
            cpa16(bb + (uint32_t)(rw * LDB1 + c16 * 8) * 2, gw + rw * 256 + c16 * 8);
        }
    };
    auto stageB2 = [&](int c) {
        uint32_t bb = sb + SM_B2(c & 1);
        const __half* gw = g_W2e + c * 32 * 128;
        #pragma unroll
        for (int i = 0; i < 4; ++i) {
            int id = tid + NTHR * i; int rw = id >> 4, c16 = id & 15;
            cpa16(bb + (uint32_t)(rw * LDB2 + c16 * 8) * 2, gw + rw * 128 + c16 * 8);
        }
    };

    // ---------------- GEMM1: [64,384]x[384,256], 12 K32 chunks ----------------
    CFrag acc[4][4];
    #pragma unroll
    for (int i = 0; i < 4; i++)
        #pragma unroll
        for (int j = 0; j < 4; j++) wmma::fill_fragment(acc[i][j], 0.f);

    ldgA(0); stageB1(0); cp_commit(); stsA(0); ldgA(1);

    #pragma unroll 1
    for (int c = 0; c < 12; ++c) {
        cp_wait0();
        __syncthreads();
        if (c + 1 < 12) { stageB1(c + 1); cp_commit(); }
        const __half* ab = (const __half*)(smc + SM_A(c & 1));
        const __half* bb = (const __half*)(smc + SM_B1(c & 1));
        #pragma unroll
        for (int kk = 0; kk < 32; kk += 16) {
            AFrag a[4];
            #pragma unroll
            for (int i = 0; i < 4; i++)
                wmma::load_matrix_sync(a[i], ab + (i * 16) * LDA + kk, LDA);
            #pragma unroll
            for (int j = 0; j < 4; j++) {
                BFrag b;
                wmma::load_matrix_sync(b, bb + kk * LDB1 + warp * 64 + j * 16, LDB1);
                #pragma unroll
                for (int i = 0; i < 4; i++)
                    wmma::mma_sync(acc[i][j], a[i], b, acc[i][j]);
            }
        }
        if (c + 1 < 12) { stsA(c + 1); if (c + 2 < 12) ldgA(c + 2); }
    }
    __syncthreads();          // GEMM1 done; B1 region dead -> HH

    stageB2(0); cp_commit();  // prefetch GEMM2 chunk 0 behind the transition

    // ---------------- transition: acc -> (bias,SiLU) -> HH fp16 --------------
    {
        float* scr = (float*)(smc + SM_SCR(warp));
        const float* sb1 = (const float*)(smc + SM_CONST_B1);
        const int rr = lane >> 1, ch = (lane & 1) * 8;
        #pragma unroll
        for (int i = 0; i < 4; i++)
            #pragma unroll
            for (int j = 0; j < 4; j++) {
                wmma::store_matrix_sync(scr, acc[i][j], LDSCR, wmma::mem_row_major);
                __syncwarp();
                const float* p = scr + rr * LDSCR + ch;
                float4 x0 = *(const float4*)(p);
                float4 x1 = *(const float4*)(p + 4);
                int cbase = warp * 64 + j * 16 + ch;
                float4 bb0 = *(const float4*)(sb1 + cbase);
                float4 bb1 = *(const float4*)(sb1 + cbase + 4);
                x0.x += bb0.x; x0.y += bb0.y; x0.z += bb0.z; x0.w += bb0.w;
                x1.x += bb1.x; x1.y += bb1.y; x1.z += bb1.z; x1.w += bb1.w;
                int rowg = i * 16 + rr;
                *(uint4*)(smc + SM_HH + (rowg * LDHH + cbase) * 2) =
                    pack8h(silu4(x0), silu4(x1));
                __syncwarp();
            }
    }

    // ---------------- GEMM2: [64,256]x[256,128], 8 K32 chunks ----------------
    CFrag acc2[4][2];
    #pragma unroll
    for (int i = 0; i < 4; i++)
        #pragma unroll
        for (int j = 0; j < 2; j++) wmma::fill_fragment(acc2[i][j], 0.f);

    const __half* hh = (const __half*)(smc + SM_HH);
    #pragma unroll 1
    for (int c = 0; c < 8; ++c) {
        cp_wait0();
        __syncthreads();
        if (c + 1 < 8) { stageB2(c + 1); cp_commit(); }
        const __half* bb = (const __half*)(smc + SM_B2(c & 1));
        #pragma unroll
        for (int kk = 0; kk < 32; kk += 16) {
            AFrag a[4];
            #pragma unroll
            for (int i = 0; i < 4; i++)
                wmma::load_matrix_sync(a[i], hh + (i * 16) * LDHH + c * 32 + kk, LDHH);
            #pragma unroll
            for (int j = 0; j < 2; j++) {
                BFrag b;
                wmma::load_matrix_sync(b, bb + kk * LDB2 + warp * 32 + j * 16, LDB2);
                #pragma unroll
                for (int i = 0; i < 4; i++)
                    wmma::mma_sync(acc2[i][j], a[i], b, acc2[i][j]);
            }
        }
    }
    __syncthreads();          // all GEMM2 MMAs done; A/HH dead -> Y
    float* yf = (float*)(smc + SM_Y);
    #pragma unroll
    for (int i = 0; i < 4; i++)
        #pragma unroll
        for (int j = 0; j < 2; j++)
            wmma::store_matrix_sync(yf + (i * 16) * LDY + warp * 32 + j * 16,
                                    acc2[i][j], LDY, wmma::mem_row_major);
    __syncthreads();

    // ---------------- +b2, LN, vector-red scatter ----------------
    float4 bb2 = *(const float4*)(smc + SM_CONST_B2 + lane * 16);
    float4 gg  = *(const float4*)(smc + SM_CONST_G  + lane * 16);
    float4 bt  = *(const float4*)(smc + SM_CONST_BT + lane * 16);
    #pragma unroll 1
    for (int i = 0; i < 16; i++) {
        int row = warp * 16 + i;
        float4 v = *(const float4*)(yf + row * LDY + lane * 4);
        v.x += bb2.x; v.y += bb2.y; v.z += bb2.z; v.w += bb2.w;
        float sum = v.x + v.y + v.z + v.w;
        float sq  = v.x * v.x + v.y * v.y + v.z * v.z + v.w * v.w;
        #pragma unroll
        for (int o = 16; o > 0; o >>= 1) {
            sum += __shfl_xor_sync(0xFFFFFFFFu, sum, o);
            sq  += __shfl_xor_sync(0xFFFFFFFFu, sq,  o);
        }
        float mean = sum * (1.f / 128.f);
        float rstd = rsqrtf(sq * (1.f / 128.f) - mean * mean + 1e-5f);
        int dn = __ldg(&dst[e0 + row]);
        float4 o;
        o.x = (v.x - mean) * rstd * gg.x + bt.x;
        o.y = (v.y - mean) * rstd * gg.y + bt.y;
        o.z = (v.z - mean) * rstd * gg.z + bt.z;
        o.w = (v.w - mean) * rstd * gg.w + bt.w;
        red_add_v4(g_agg + (size_t)dn * 128 + lane * 4, o);
    }
}

// ------------------------------ node kernel ---------------------------------
__global__ void __launch_bounds__(NTHR, 2)
node_kernel(const float* __restrict__ gridf,
            const float* __restrict__ b1, const float* __restrict__ b2,
            const float* __restrict__ gam, const float* __restrict__ bet,
            float* __restrict__ out)
{
    extern __shared__ char smc[];
    const uint32_t sb = smem_u32(smc);
    const int tid  = threadIdx.x;
    const int warp = tid >> 5, lane = tid & 31;
    const int n0 = blockIdx.x * MT;

    if (tid < 64) ((float4*)(smc + SM_CONST_B1))[tid] = ((const float4*)b1)[tid];
    else if (tid < 96)  ((float4*)(smc + SM_CONST_B2))[tid - 64] = ((const float4*)b2)[tid - 64];
    else if (tid < 128) ((float4*)(smc + SM_CONST_G ))[tid - 96] = ((const float4*)gam)[tid - 96];
    if (tid < 32) ((float4*)(smc + SM_CONST_BT))[tid] = ((const float4*)bet)[tid];

    const int r  = tid >> 1;
    const int cb = (tid & 1) * 16;
    const float* rowA = g_agg + (size_t)(n0 + r) * 128;
    const float* rowG = gridf + (size_t)(n0 + r) * 128;

    float4 v0, v1, v2, v3;
    auto ldgA = [&](int c) {
        const float* rp = (c < 4) ? rowA : rowG;
        const float4* gp = (const float4*)(rp + (c & 3) * 32 + cb);
        v0 = __ldg(gp); v1 = __ldg(gp + 1); v2 = __ldg(gp + 2); v3 = __ldg(gp + 3);
    };
    auto stsA = [&](int c) {
        char* d = smc + SM_A(c & 1) + (r * LDA + cb) * 2;
        *(uint4*)(d)      = pack8h(v0, v1);
        *(uint4*)(d + 16) = pack8h(v2, v3);
    };
    auto stageB1 = [&](int c) {
        uint32_t bb = sb + SM_B1(c & 1);
        const __half* gw = g_W1n + c * 32 * 256;
        #pragma unroll
        for (int i = 0; i < 8; ++i) {
            int id = tid + NTHR * i; int rw = id >> 5, c16 = id & 31;
            cpa16(bb + (uint32_t)(rw * LDB1 + c16 * 8) * 2, gw + rw * 256 + c16 * 8);
        }
    };
    auto stageB2 = [&](int c) {
        uint32_t bb = sb + SM_B2(c & 1);
        const __half* gw = g_W2n + c * 32 * 128;
        #pragma unroll
        for (int i = 0; i < 4; ++i) {
            int id = tid + NTHR * i; int rw = id >> 4, c16 = id & 15;
            cpa16(bb + (uint32_t)(rw * LDB2 + c16 * 8) * 2, gw + rw * 128 + c16 * 8);
        }
    };

    // ---------------- GEMM1: [64,256]x[256,256], 8 K32 chunks ----------------
    CFrag acc[4][4];
    #pragma unroll
    for (int i = 0; i < 4; i++)
        #pragma unroll
        for (int j = 0; j < 4; j++) wmma::fill_fragment(acc[i][j], 0.f);

    ldgA(0); stageB1(0); cp_commit(); stsA(0); ldgA(1);

    #pragma unroll 1
    for (int c = 0; c < 8; ++c) {
        cp_wait0();
        __syncthreads();
        if (c + 1 < 8) { stageB1(c + 1); cp_commit(); }
        const __half* ab = (const __half*)(smc + SM_A(c & 1));
        const __half* bb = (const __half*)(smc + SM_B1(c & 1));
        #pragma unroll
        for (int kk = 0; kk < 32; kk += 16) {
            AFrag a[4];
            #pragma unroll
            for (int i = 0; i < 4; i++)
                wmma::load_matrix_sync(a[i], ab + (i * 16) * LDA + kk, LDA);
            #pragma unroll
            for (int j = 0; j < 4; j++) {
                BFrag b;
                wmma::load_matrix_sync(b, bb + kk * LDB1 + warp * 64 + j * 16, LDB1);
                #pragma unroll
                for (int i = 0; i < 4; i++)
                    wmma::mma_sync(acc[i][j], a[i], b, acc[i][j]);
            }
        }
        if (c + 1 < 8) { stsA(c + 1); if (c + 2 < 8) ldgA(c + 2); }
    }
    __syncthreads();

    stageB2(0); cp_commit();

    // ---------------- transition: acc -> (bias,SiLU) -> HH fp16 --------------
    {
        float* scr = (float*)(smc + SM_SCR(warp));
        const float* sb1 = (const float*)(smc + SM_CONST_B1);
        const int rr = lane >> 1, ch = (lane & 1) * 8;
        #pragma unroll
        for (int i = 0; i < 4; i++)
            #pragma unroll
            for (int j = 0; j < 4; j++) {
                wmma::store_matrix_sync(scr, acc[i][j], LDSCR, wmma::mem_row_major);
                __syncwarp();
                const float* p = scr + rr * LDSCR + ch;
                float4 x0 = *(const float4*)(p);
                float4 x1 = *(const float4*)(p + 4);
                int cbase = warp * 64 + j * 16 + ch;
                float4 bb0 = *(const float4*)(sb1 + cbase);
                float4 bb1 = *(const float4*)(sb1 + cbase + 4);
                x0.x += bb0.x; x0.y += bb0.y; x0.z += bb0.z; x0.w += bb0.w;
                x1.x += bb1.x; x1.y += bb1.y; x1.z += bb1.z; x1.w += bb1.w;
                int rowg = i * 16 + rr;
                *(uint4*)(smc + SM_HH + (rowg * LDHH + cbase) * 2) =
                    pack8h(silu4(x0), silu4(x1));
                __syncwarp();
            }
    }

    // ---------------- GEMM2: [64,256]x[256,128], 8 K32 chunks ----------------
    CFrag acc2[4][2];
    #pragma unroll
    for (int i = 0; i < 4; i++)
        #pragma unroll
        for (int j = 0; j < 2; j++) wmma::fill_fragment(acc2[i][j], 0.f);

    const __half* hh = (const __half*)(smc + SM_HH);
    #pragma unroll 1
    for (int c = 0; c < 8; ++c) {
        cp_wait0();
        __syncthreads();
        if (c + 1 < 8) { stageB2(c + 1); cp_commit(); }
        const __half* bb = (const __half*)(smc + SM_B2(c & 1));
        #pragma unroll
        for (int kk = 0; kk < 32; kk += 16) {
            AFrag a[4];
            #pragma unroll
            for (int i = 0; i < 4; i++)
                wmma::load_matrix_sync(a[i], hh + (i * 16) * LDHH + c * 32 + kk, LDHH);
            #pragma unroll
            for (int j = 0; j < 2; j++) {
                BFrag b;
                wmma::load_matrix_sync(b, bb + kk * LDB2 + warp * 32 + j * 16, LDB2);
                #pragma unroll
                for (int i = 0; i < 4; i++)
                    wmma::mma_sync(acc2[i][j], a[i], b, acc2[i][j]);
            }
        }
    }
    __syncthreads();
    float* yf = (float*)(smc + SM_Y);
    #pragma unroll
    for (int i = 0; i < 4; i++)
        #pragma unroll
        for (int j = 0; j < 2; j++)
            wmma::store_matrix_sync(yf + (i * 16) * LDY + warp * 32 + j * 16,
                                    acc2[i][j], LDY, wmma::mem_row_major);
    __syncthreads();

    // ---------------- +b2, LN, affine, +residual ----------------
    float4 bb2 = *(const float4*)(smc + SM_CONST_B2 + lane * 16);
    float4 gg  = *(const float4*)(smc + SM_CONST_G  + lane * 16);
    float4 bt  = *(const float4*)(smc + SM_CONST_BT + lane * 16);
    #pragma unroll 1
    for (int i = 0; i < 16; i++) {
        int row = warp * 16 + i;
        float4 v = *(const float4*)(yf + row * LDY + lane * 4);
        v.x += bb2.x; v.y += bb2.y; v.z += bb2.z; v.w += bb2.w;
        float sum = v.x + v.y + v.z + v.w;
        float sq  = v.x * v.x + v.y * v.y + v.z * v.z + v.w * v.w;
        #pragma unroll
        for (int o = 16; o > 0; o >>= 1) {
            sum += __shfl_xor_sync(0xFFFFFFFFu, sum, o);
            sq  += __shfl_xor_sync(0xFFFFFFFFu, sq,  o);
        }
        float mean = sum * (1.f / 128.f);
        float rstd = rsqrtf(sq * (1.f / 128.f) - mean * mean + 1e-5f);
        size_t base = (size_t)(n0 + row) * 128;
        float4 gv = __ldg((const float4*)(gridf + base) + lane);
        float4 o;
        o.x = (v.x - mean) * rstd * gg.x + bt.x + gv.x;
        o.y = (v.y - mean) * rstd * gg.y + bt.y + gv.y;
        o.z = (v.z - mean) * rstd * gg.z + bt.z + gv.z;
        o.w = (v.w - mean) * rstd * gg.w + bt.w + gv.w;
        *((float4*)(out + base) + lane) = o;
    }
}

// ------------------------------ launch --------------------------------------
extern "C" void kernel_launch(void* const* d_in, const int* in_sizes, int n_in,
                              void* d_out, int out_size)
{
    const float* efeat = (const float*)d_in[0];
    const float* gridf = (const float*)d_in[1];
    const float* mesh  = (const float*)d_in[2];
    const int*   src   = (const int*)d_in[3];
    const int*   dst   = (const int*)d_in[4];
    const float* eW1   = (const float*)d_in[5];
    const float* eb1   = (const float*)d_in[6];
    const float* eW2   = (const float*)d_in[7];
    const float* eb2   = (const float*)d_in[8];
    const float* eg    = (const float*)d_in[9];
    const float* ebeta = (const float*)d_in[10];
    const float* nW1   = (const float*)d_in[11];
    const float* nb1   = (const float*)d_in[12];
    const float* nW2   = (const float*)d_in[13];
    const float* nb2   = (const float*)d_in[14];
    const float* ng    = (const float*)d_in[15];
    const float* nbeta = (const float*)d_in[16];
    float* out = (float*)d_out;

    cudaFuncSetAttribute(edge_kernel, cudaFuncAttributeMaxDynamicSharedMemorySize, SMEM_BYTES);
    cudaFuncSetAttribute(node_kernel, cudaFuncAttributeMaxDynamicSharedMemorySize, SMEM_BYTES);

    zero_agg_kernel<<<8192, 1024>>>();
    prep_kernel<<<896, 256>>>(eW1, eW2, nW1, nW2);
    edge_kernel<<<N_EDGE / MT, NTHR, SMEM_BYTES>>>(efeat, gridf, mesh, src, dst,
                                                   eb1, eb2, eg, ebeta);
    node_kernel<<<N_GRID / MT, NTHR, SMEM_BYTES>>>(gridf, nb1, nb2, ng, nbeta, out);
}

// round 12
// speedup vs baseline: 2.3038x; 1.1864x over previous
#include <cuda_runtime.h>
#include <cuda_fp16.h>
#include <mma.h>
#include <cstdint>

using namespace nvcuda;

#define N_MESH 40962
#define N_GRID 262144
#define N_EDGE 786432

// ------------------------------ device scratch ------------------------------
__device__ __half g_aggh[(size_t)N_GRID * 128];   // fp16 aggregation buffer
__device__ __half g_W1e[384 * 256];   // [K][N], fp16-RN pre-rounded
__device__ __half g_W2e[256 * 128];
__device__ __half g_W1n[256 * 256];
__device__ __half g_W2n[256 * 128];

#define MT    64
#define NTHR  256

// ------------------------------ smem layout (BYTE offsets) ------------------
#define SM_CONST_B1 0
#define SM_CONST_B2 1024
#define SM_CONST_G  1536
#define SM_CONST_BT 2048
#define SM_A(b)    (2560 + (b) * 9216)      // half, 64 x 72, double buffer
#define SM_B1(s)   (20992 + (s) * 33792)    // half, 64 x 264, double buffer
#define SM_B2(s)   (20992 + (s) * 17408)    // half, 64 x 136, double (in B1 space)
#define SM_HH      55808                     // half, 64 x 264 (in dead B1 buf1)
#define SM_SCR(w)  (89600 + (w) * 1280)     // float, 16 x 20 per-warp scratch
#define SM_Y       20992                     // float, 64 x 132 (B2 dead by then)
#define SMEM_BYTES 99840                     // x2 CTAs = 199,680 <= 227KB/SM

#define LDA   72
#define LDB1  264
#define LDB2  136
#define LDHH  264
#define LDY   132
#define LDSCR 20

// ------------------------------ helpers -------------------------------------
__device__ __forceinline__ uint32_t smem_u32(const void* p) {
    uint32_t a;
    asm("{ .reg .u64 t; cvta.to.shared.u64 t, %1; cvt.u32.u64 %0, t; }" : "=r"(a) : "l"(p));
    return a;
}
__device__ __forceinline__ void cpa16(uint32_t s, const void* g) {
    asm volatile("cp.async.cg.shared.global [%0], [%1], 16;" :: "r"(s), "l"(g) : "memory");
}
__device__ __forceinline__ void cp_commit() {
    asm volatile("cp.async.commit_group;" ::: "memory");
}
__device__ __forceinline__ void cp_wait0() {
    asm volatile("cp.async.wait_group 0;" ::: "memory");
}
// vectorized fp16 scatter-add: 4 halves (8 bytes) per op
__device__ __forceinline__ void red_add_h4(__half* p, float4 v) {
    __half2 h01 = __floats2half2_rn(v.x, v.y);
    __half2 h23 = __floats2half2_rn(v.z, v.w);
    uint32_t u0 = *reinterpret_cast<uint32_t*>(&h01);
    uint32_t u1 = *reinterpret_cast<uint32_t*>(&h23);
    asm volatile("red.global.add.noftz.v2.f16x2 [%0], {%1, %2};"
                 :: "l"(p), "r"(u0), "r"(u1) : "memory");
}
__device__ __forceinline__ uint4 pack8h(float4 a, float4 b) {
    __half2 h0 = __floats2half2_rn(a.x, a.y);
    __half2 h1 = __floats2half2_rn(a.z, a.w);
    __half2 h2 = __floats2half2_rn(b.x, b.y);
    __half2 h3 = __floats2half2_rn(b.z, b.w);
    uint4 u;
    u.x = *reinterpret_cast<uint32_t*>(&h0);
    u.y = *reinterpret_cast<uint32_t*>(&h1);
    u.z = *reinterpret_cast<uint32_t*>(&h2);
    u.w = *reinterpret_cast<uint32_t*>(&h3);
    return u;
}
__device__ __forceinline__ float4 silu4(float4 x) {
    float4 s;
    s.x = x.x / (1.f + __expf(-x.x)); s.y = x.y / (1.f + __expf(-x.y));
    s.z = x.z / (1.f + __expf(-x.z)); s.w = x.w / (1.f + __expf(-x.w));
    return s;
}

typedef wmma::fragment<wmma::matrix_a, 16, 16, 16, __half, wmma::row_major> AFrag;
typedef wmma::fragment<wmma::matrix_b, 16, 16, 16, __half, wmma::row_major> BFrag;
typedef wmma::fragment<wmma::accumulator, 16, 16, 16, float> CFrag;

// ------------------------------ prep kernels --------------------------------
__global__ void zero_agg_kernel() {
    size_t i = (size_t)blockIdx.x * blockDim.x + threadIdx.x;  // 4,194,304 uint4
    reinterpret_cast<uint4*>(g_aggh)[i] = make_uint4(0u, 0u, 0u, 0u);
}
__global__ void prep_kernel(const float* __restrict__ eW1, const float* __restrict__ eW2,
                            const float* __restrict__ nW1, const float* __restrict__ nW2) {
    int i = blockIdx.x * blockDim.x + threadIdx.x;
    if (i < 98304)       g_W1e[i]          = __float2half_rn(eW1[i]);
    else if (i < 131072) g_W2e[i - 98304]  = __float2half_rn(eW2[i - 98304]);
    else if (i < 196608) g_W1n[i - 131072] = __float2half_rn(nW1[i - 131072]);
    else if (i < 229376) g_W2n[i - 196608] = __float2half_rn(nW2[i - 196608]);
}

// ------------------------------ edge kernel ---------------------------------
// tile = 64 edges; K-chunks of 64. GEMM1 6 chunks, GEMM2 4 chunks.
__global__ void __launch_bounds__(NTHR, 2)
edge_kernel(const float* __restrict__ efeat, const float* __restrict__ gridf,
            const float* __restrict__ mesh, const int* __restrict__ src,
            const int* __restrict__ dst,
            const float* __restrict__ b1, const float* __restrict__ b2,
            const float* __restrict__ gam, const float* __restrict__ bet)
{
    extern __shared__ char smc[];
    const uint32_t sb = smem_u32(smc);
    const int tid  = threadIdx.x;
    const int warp = tid >> 5, lane = tid & 31;
    const int wm = warp >> 2, wn = warp & 3;
    const int e0 = blockIdx.x * MT;

    if (tid < 64) ((float4*)(smc + SM_CONST_B1))[tid] = ((const float4*)b1)[tid];
    else if (tid < 96)  ((float4*)(smc + SM_CONST_B2))[tid - 64] = ((const float4*)b2)[tid - 64];
    else if (tid < 128) ((float4*)(smc + SM_CONST_G ))[tid - 96] = ((const float4*)gam)[tid - 96];
    else if (tid < 160) ((float4*)(smc + SM_CONST_BT))[tid - 128] = ((const float4*)bet)[tid - 128];

    // gather: 4 threads/row, 16 floats each
    const int r  = tid >> 2;
    const int cb = (tid & 3) * 16;
    const int sidx = __ldg(&src[e0 + r]);
    const int didx = __ldg(&dst[e0 + r]);
    const float* rowE = efeat + (size_t)(e0 + r) * 128;
    const float* rowM = mesh  + (size_t)sidx * 128;
    const float* rowG = gridf + (size_t)didx * 128;

    float4 v0, v1, v2, v3;
    auto ldgA = [&](int c) {
        const float* rp = (c < 2) ? rowE : (c < 4) ? rowM : rowG;
        const float4* gp = (const float4*)(rp + (c & 1) * 64 + cb);
        v0 = __ldg(gp); v1 = __ldg(gp + 1); v2 = __ldg(gp + 2); v3 = __ldg(gp + 3);
    };
    auto stsA = [&](int c) {
        char* d = smc + SM_A(c & 1) + (r * LDA + cb) * 2;
        *(uint4*)(d)      = pack8h(v0, v1);
        *(uint4*)(d + 16) = pack8h(v2, v3);
    };
    auto stageB1 = [&](int c) {
        uint32_t bb = sb + SM_B1(c & 1);
        const __half* gw = g_W1e + c * 64 * 256;
        #pragma unroll
        for (int i = 0; i < 8; ++i) {
            int id = tid + NTHR * i; int rw = id >> 5, c16 = id & 31;
            cpa16(bb + (uint32_t)(rw * LDB1 + c16 * 8) * 2, gw + rw * 256 + c16 * 8);
        }
    };
    auto stageB2 = [&](int c) {
        uint32_t bb = sb + SM_B2(c & 1);
        const __half* gw = g_W2e + c * 64 * 128;
        #pragma unroll
        for (int i = 0; i < 4; ++i) {
            int id = tid + NTHR * i; int rw = id >> 4, c16 = id & 15;
            cpa16(bb + (uint32_t)(rw * LDB2 + c16 * 8) * 2, gw + rw * 128 + c16 * 8);
        }
    };

    // ---------------- GEMM1: [64,384]x[384,256], 6 K64-chunks ----------------
    CFrag acc[2][4];
    #pragma unroll
    for (int i = 0; i < 2; i++)
        #pragma unroll
        for (int j = 0; j < 4; j++) wmma::fill_fragment(acc[i][j], 0.f);

    ldgA(0);
    stageB1(0); cp_commit();
    stsA(0);
    ldgA(1);

    #pragma unroll 1
    for (int c = 0; c < 6; ++c) {
        cp_wait0();
        __syncthreads();
        if (c + 1 < 6) { stageB1(c + 1); cp_commit(); }
        const __half* ab = (const __half*)(smc + SM_A(c & 1));
        const __half* bb = (const __half*)(smc + SM_B1(c & 1));
        #pragma unroll
        for (int kk = 0; kk < 64; kk += 16) {
            AFrag a0, a1;
            wmma::load_matrix_sync(a0, ab + (wm * 32)      * LDA + kk, LDA);
            wmma::load_matrix_sync(a1, ab + (wm * 32 + 16) * LDA + kk, LDA);
            #pragma unroll
            for (int j = 0; j < 4; j++) {
                BFrag b;
                wmma::load_matrix_sync(b, bb + kk * LDB1 + wn * 64 + j * 16, LDB1);
                wmma::mma_sync(acc[0][j], a0, b, acc[0][j]);
                wmma::mma_sync(acc[1][j], a1, b, acc[1][j]);
            }
        }
        if (c + 1 < 6) { stsA(c + 1); if (c + 2 < 6) ldgA(c + 2); }
    }
    __syncthreads();

    stageB2(0); cp_commit();  // prefetch GEMM2 chunk 0 behind the transition

    // ---------------- transition: acc -> (bias,SiLU) -> HH fp16 --------------
    {
        float* scr = (float*)(smc + SM_SCR(warp));
        const float* sb1 = (const float*)(smc + SM_CONST_B1);
        const int rr = lane >> 1, ch = (lane & 1) * 8;
        #pragma unroll
        for (int i = 0; i < 2; i++)
            #pragma unroll
            for (int j = 0; j < 4; j++) {
                wmma::store_matrix_sync(scr, acc[i][j], LDSCR, wmma::mem_row_major);
                __syncwarp();
                const float* p = scr + rr * LDSCR + ch;
                float4 x0 = *(const float4*)(p);
                float4 x1 = *(const float4*)(p + 4);
                int cbase = wn * 64 + j * 16 + ch;
                float4 bb0 = *(const float4*)(sb1 + cbase);
                float4 bb1 = *(const float4*)(sb1 + cbase + 4);
                x0.x += bb0.x; x0.y += bb0.y; x0.z += bb0.z; x0.w += bb0.w;
                x1.x += bb1.x; x1.y += bb1.y; x1.z += bb1.z; x1.w += bb1.w;
                int rowg = wm * 32 + i * 16 + rr;
                *(uint4*)(smc + SM_HH + (rowg * LDHH + cbase) * 2) =
                    pack8h(silu4(x0), silu4(x1));
                __syncwarp();
            }
    }

    // ---------------- GEMM2: [64,256]x[256,128], 4 K64-chunks ----------------
    CFrag acc2[2][2];
    #pragma unroll
    for (int i = 0; i < 2; i++)
        #pragma unroll
        for (int j = 0; j < 2; j++) wmma::fill_fragment(acc2[i][j], 0.f);

    const __half* hh = (const __half*)(smc + SM_HH);
    #pragma unroll 1
    for (int c = 0; c < 4; ++c) {
        cp_wait0();
        __syncthreads();
        if (c + 1 < 4) { stageB2(c + 1); cp_commit(); }
        const __half* bb = (const __half*)(smc + SM_B2(c & 1));
        #pragma unroll
        for (int kk = 0; kk < 64; kk += 16) {
            AFrag a0, a1;
            wmma::load_matrix_sync(a0, hh + (wm * 32)      * LDHH + c * 64 + kk, LDHH);
            wmma::load_matrix_sync(a1, hh + (wm * 32 + 16) * LDHH + c * 64 + kk, LDHH);
            #pragma unroll
            for (int j = 0; j < 2; j++) {
                BFrag b;
                wmma::load_matrix_sync(b, bb + kk * LDB2 + wn * 32 + j * 16, LDB2);
                wmma::mma_sync(acc2[0][j], a0, b, acc2[0][j]);
                wmma::mma_sync(acc2[1][j], a1, b, acc2[1][j]);
            }
        }
    }
    __syncthreads();
    float* yf = (float*)(smc + SM_Y);
    #pragma unroll
    for (int i = 0; i < 2; i++)
        #pragma unroll
        for (int j = 0; j < 2; j++)
            wmma::store_matrix_sync(yf + (wm * 32 + i * 16) * LDY + wn * 32 + j * 16,
                                    acc2[i][j], LDY, wmma::mem_row_major);
    __syncthreads();

    // ---------------- +b2, LN, fp16 vector-red scatter ----------------
    float4 bb2 = *(const float4*)(smc + SM_CONST_B2 + lane * 16);
    float4 gg  = *(const float4*)(smc + SM_CONST_G  + lane * 16);
    float4 bt  = *(const float4*)(smc + SM_CONST_BT + lane * 16);
    #pragma unroll 1
    for (int i = 0; i < 8; i++) {
        int row = warp * 8 + i;
        float4 v = *(const float4*)(yf + row * LDY + lane * 4);
        v.x += bb2.x; v.y += bb2.y; v.z += bb2.z; v.w += bb2.w;
        float sum = v.x + v.y + v.z + v.w;
        float sq  = v.x * v.x + v.y * v.y + v.z * v.z + v.w * v.w;
        #pragma unroll
        for (int o = 16; o > 0; o >>= 1) {
            sum += __shfl_xor_sync(0xFFFFFFFFu, sum, o);
            sq  += __shfl_xor_sync(0xFFFFFFFFu, sq,  o);
        }
        float mean = sum * (1.f / 128.f);
        float rstd = rsqrtf(sq * (1.f / 128.f) - mean * mean + 1e-5f);
        int dn = __ldg(&dst[e0 + row]);
        float4 o;
        o.x = (v.x - mean) * rstd * gg.x + bt.x;
        o.y = (v.y - mean) * rstd * gg.y + bt.y;
        o.z = (v.z - mean) * rstd * gg.z + bt.z;
        o.w = (v.w - mean) * rstd * gg.w + bt.w;
        red_add_h4(g_aggh + (size_t)dn * 128 + lane * 4, o);
    }
}

// ------------------------------ node kernel ---------------------------------
__global__ void __launch_bounds__(NTHR, 2)
node_kernel(const float* __restrict__ gridf,
            const float* __restrict__ b1, const float* __restrict__ b2,
            const float* __restrict__ gam, const float* __restrict__ bet,
            float* __restrict__ out)
{
    extern __shared__ char smc[];
    const uint32_t sb = smem_u32(smc);
    const int tid  = threadIdx.x;
    const int warp = tid >> 5, lane = tid & 31;
    const int wm = warp >> 2, wn = warp & 3;
    const int n0 = blockIdx.x * MT;

    if (tid < 64) ((float4*)(smc + SM_CONST_B1))[tid] = ((const float4*)b1)[tid];
    else if (tid < 96)  ((float4*)(smc + SM_CONST_B2))[tid - 64] = ((const float4*)b2)[tid - 64];
    else if (tid < 128) ((float4*)(smc + SM_CONST_G ))[tid - 96] = ((const float4*)gam)[tid - 96];
    else if (tid < 160) ((float4*)(smc + SM_CONST_BT))[tid - 128] = ((const float4*)bet)[tid - 128];

    const int r  = tid >> 2;
    const int cb = (tid & 3) * 16;
    const __half* rowA = g_aggh + (size_t)(n0 + r) * 128;
    const float*  rowG = gridf  + (size_t)(n0 + r) * 128;

    float4 v0, v1, v2, v3;     // grid-path staging (fp32)
    uint4  h0, h1;             // agg-path staging (fp16, raw copy)
    auto ldgA = [&](int c) {
        if (c < 2) {
            const uint4* gp = (const uint4*)(rowA + (c & 1) * 64 + cb);
            h0 = __ldg(gp); h1 = __ldg(gp + 1);
        } else {
            const float4* gp = (const float4*)(rowG + (c & 1) * 64 + cb);
            v0 = __ldg(gp); v1 = __ldg(gp + 1); v2 = __ldg(gp + 2); v3 = __ldg(gp + 3);
        }
    };
    auto stsA = [&](int c) {
        char* d = smc + SM_A(c & 1) + (r * LDA + cb) * 2;
        if (c < 2) {
            *(uint4*)(d)      = h0;
            *(uint4*)(d + 16) = h1;
        } else {
            *(uint4*)(d)      = pack8h(v0, v1);
            *(uint4*)(d + 16) = pack8h(v2, v3);
        }
    };
    auto stageB1 = [&](int c) {
        uint32_t bb = sb + SM_B1(c & 1);
        const __half* gw = g_W1n + c * 64 * 256;
        #pragma unroll
        for (int i = 0; i < 8; ++i) {
            int id = tid + NTHR * i; int rw = id >> 5, c16 = id & 31;
            cpa16(bb + (uint32_t)(rw * LDB1 + c16 * 8) * 2, gw + rw * 256 + c16 * 8);
        }
    };
    auto stageB2 = [&](int c) {
        uint32_t bb = sb + SM_B2(c & 1);
        const __half* gw = g_W2n + c * 64 * 128;
        #pragma unroll
        for (int i = 0; i < 4; ++i) {
            int id = tid + NTHR * i; int rw = id >> 4, c16 = id & 15;
            cpa16(bb + (uint32_t)(rw * LDB2 + c16 * 8) * 2, gw + rw * 128 + c16 * 8);
        }
    };

    // ---------------- GEMM1: [64,256]x[256,256], 4 K64-chunks ----------------
    CFrag acc[2][4];
    #pragma unroll
    for (int i = 0; i < 2; i++)
        #pragma unroll
        for (int j = 0; j < 4; j++) wmma::fill_fragment(acc[i][j], 0.f);

    ldgA(0);
    stageB1(0); cp_commit();
    stsA(0);
    ldgA(1);

    #pragma unroll 1
    for (int c = 0; c < 4; ++c) {
        cp_wait0();
        __syncthreads();
        if (c + 1 < 4) { stageB1(c + 1); cp_commit(); }
        const __half* ab = (const __half*)(smc + SM_A(c & 1));
        const __half* bb = (const __half*)(smc + SM_B1(c & 1));
        #pragma unroll
        for (int kk = 0; kk < 64; kk += 16) {
            AFrag a0, a1;
            wmma::load_matrix_sync(a0, ab + (wm * 32)      * LDA + kk, LDA);
            wmma::load_matrix_sync(a1, ab + (wm * 32 + 16) * LDA + kk, LDA);
            #pragma unroll
            for (int j = 0; j < 4; j++) {
                BFrag b;
                wmma::load_matrix_sync(b, bb + kk * LDB1 + wn * 64 + j * 16, LDB1);
                wmma::mma_sync(acc[0][j], a0, b, acc[0][j]);
                wmma::mma_sync(acc[1][j], a1, b, acc[1][j]);
            }
        }
        if (c + 1 < 4) { stsA(c + 1); if (c + 2 < 4) ldgA(c + 2); }
    }
    __syncthreads();

    stageB2(0); cp_commit();

    // ---------------- transition: acc -> (bias,SiLU) -> HH fp16 --------------
    {
        float* scr = (float*)(smc + SM_SCR(warp));
        const float* sb1 = (const float*)(smc + SM_CONST_B1);
        const int rr = lane >> 1, ch = (lane & 1) * 8;
        #pragma unroll
        for (int i = 0; i < 2; i++)
            #pragma unroll
            for (int j = 0; j < 4; j++) {
                wmma::store_matrix_sync(scr, acc[i][j], LDSCR, wmma::mem_row_major);
                __syncwarp();
                const float* p = scr + rr * LDSCR + ch;
                float4 x0 = *(const float4*)(p);
                float4 x1 = *(const float4*)(p + 4);
                int cbase = wn * 64 + j * 16 + ch;
                float4 bb0 = *(const float4*)(sb1 + cbase);
                float4 bb1 = *(const float4*)(sb1 + cbase + 4);
                x0.x += bb0.x; x0.y += bb0.y; x0.z += bb0.z; x0.w += bb0.w;
                x1.x += bb1.x; x1.y += bb1.y; x1.z += bb1.z; x1.w += bb1.w;
                int rowg = wm * 32 + i * 16 + rr;
                *(uint4*)(smc + SM_HH + (rowg * LDHH + cbase) * 2) =
                    pack8h(silu4(x0), silu4(x1));
                __syncwarp();
            }
    }

    // ---------------- GEMM2: [64,256]x[256,128], 4 K64-chunks ----------------
    CFrag acc2[2][2];
    #pragma unroll
    for (int i = 0; i < 2; i++)
        #pragma unroll
        for (int j = 0; j < 2; j++) wmma::fill_fragment(acc2[i][j], 0.f);

    const __half* hh = (const __half*)(smc + SM_HH);
    #pragma unroll 1
    for (int c = 0; c < 4; ++c) {
        cp_wait0();
        __syncthreads();
        if (c + 1 < 4) { stageB2(c + 1); cp_commit(); }
        const __half* bb = (const __half*)(smc + SM_B2(c & 1));
        #pragma unroll
        for (int kk = 0; kk < 64; kk += 16) {
            AFrag a0, a1;
            wmma::load_matrix_sync(a0, hh + (wm * 32)      * LDHH + c * 64 + kk, LDHH);
            wmma::load_matrix_sync(a1, hh + (wm * 32 + 16) * LDHH + c * 64 + kk, LDHH);
            #pragma unroll
            for (int j = 0; j < 2; j++) {
                BFrag b;
                wmma::load_matrix_sync(b, bb + kk * LDB2 + wn * 32 + j * 16, LDB2);
                wmma::mma_sync(acc2[0][j], a0, b, acc2[0][j]);
                wmma::mma_sync(acc2[1][j], a1, b, acc2[1][j]);
            }
        }
    }
    __syncthreads();
    float* yf = (float*)(smc + SM_Y);
    #pragma unroll
    for (int i = 0; i < 2; i++)
        #pragma unroll
        for (int j = 0; j < 2; j++)
            wmma::store_matrix_sync(yf + (wm * 32 + i * 16) * LDY + wn * 32 + j * 16,
                                    acc2[i][j], LDY, wmma::mem_row_major);
    __syncthreads();

    // ---------------- +b2, LN, affine, +residual ----------------
    float4 bb2 = *(const float4*)(smc + SM_CONST_B2 + lane * 16);
    float4 gg  = *(const float4*)(smc + SM_CONST_G  + lane * 16);
    float4 bt  = *(const float4*)(smc + SM_CONST_BT + lane * 16);
    #pragma unroll 1
    for (int i = 0; i < 8; i++) {
        int row = warp * 8 + i;
        float4 v = *(const float4*)(yf + row * LDY + lane * 4);
        v.x += bb2.x; v.y += bb2.y; v.z += bb2.z; v.w += bb2.w;
        float sum = v.x + v.y + v.z + v.w;
        float sq  = v.x * v.x + v.y * v.y + v.z * v.z + v.w * v.w;
        #pragma unroll
        for (int o = 16; o > 0; o >>= 1) {
            sum += __shfl_xor_sync(0xFFFFFFFFu, sum, o);
            sq  += __shfl_xor_sync(0xFFFFFFFFu, sq,  o);
        }
        float mean = sum * (1.f / 128.f);
        float rstd = rsqrtf(sq * (1.f / 128.f) - mean * mean + 1e-5f);
        size_t base = (size_t)(n0 + row) * 128;
        float4 gv = __ldg((const float4*)(gridf + base) + lane);
        float4 o;
        o.x = (v.x - mean) * rstd * gg.x + bt.x + gv.x;
        o.y = (v.y - mean) * rstd * gg.y + bt.y + gv.y;
        o.z = (v.z - mean) * rstd * gg.z + bt.z + gv.z;
        o.w = (v.w - mean) * rstd * gg.w + bt.w + gv.w;
        *((float4*)(out + base) + lane) = o;
    }
}

// ------------------------------ launch --------------------------------------
extern "C" void kernel_launch(void* const* d_in, const int* in_sizes, int n_in,
                              void* d_out, int out_size)
{
    const float* efeat = (const float*)d_in[0];
    const float* gridf = (const float*)d_in[1];
    const float* mesh  = (const float*)d_in[2];
    const int*   src   = (const int*)d_in[3];
    const int*   dst   = (const int*)d_in[4];
    const float* eW1   = (const float*)d_in[5];
    const float* eb1   = (const float*)d_in[6];
    const float* eW2   = (const float*)d_in[7];
    const float* eb2   = (const float*)d_in[8];
    const float* eg    = (const float*)d_in[9];
    const float* ebeta = (const float*)d_in[10];
    const float* nW1   = (const float*)d_in[11];
    const float* nb1   = (const float*)d_in[12];
    const float* nW2   = (const float*)d_in[13];
    const float* nb2   = (const float*)d_in[14];
    const float* ng    = (const float*)d_in[15];
    const float* nbeta = (const float*)d_in[16];
    float* out = (float*)d_out;

    cudaFuncSetAttribute(edge_kernel, cudaFuncAttributeMaxDynamicSharedMemorySize, SMEM_BYTES);
    cudaFuncSetAttribute(node_kernel, cudaFuncAttributeMaxDynamicSharedMemorySize, SMEM_BYTES);

    zero_agg_kernel<<<4096, 1024>>>();
    prep_kernel<<<896, 256>>>(eW1, eW2, nW1, nW2);
    edge_kernel<<<N_EDGE / MT, NTHR, SMEM_BYTES>>>(efeat, gridf, mesh, src, dst,
                                                   eb1, eb2, eg, ebeta);
    node_kernel<<<N_GRID / MT, NTHR, SMEM_BYTES>>>(gridf, nb1, nb2, ng, nbeta, out);
}